// round 2
// baseline (speedup 1.0000x reference)
#include <cuda_runtime.h>

// Problem constants (fixed shapes from setup_inputs)
#define NB      64
#define T_LEN   2048
#define DDIM    80
#define N_ELEM  (NB * T_LEN * DDIM)   // 10,485,760
#define N_VEC   (N_ELEM / 4)          // 2,621,440 float4 elements
#define VPR     (DDIM / 4)            // 20 float4 per row

#define GBLOCKS 1184                  // 8 CTAs per SM on 148 SMs
#define GTHREADS 256

// Scratch (no allocation allowed): per-block partials + completion ticket
__device__ float        g_pc[GBLOCKS];   // sum of scaled center diffs
__device__ float        g_pl[GBLOCKS];   // sum of lg2(s)
__device__ unsigned int g_count = 0;     // self-resetting ticket

__device__ __forceinline__ float ex2f(float x) {
    float y; asm("ex2.approx.f32 %0, %1;" : "=f"(y) : "f"(x)); return y;
}
__device__ __forceinline__ float lg2f(float x) {
    float y; asm("lg2.approx.f32 %0, %1;" : "=f"(y) : "f"(x)); return y;
}

__global__ void __launch_bounds__(GTHREADS)
jitter_fused(const float* __restrict__ in, const float* __restrict__ tg,
             float* __restrict__ out)
{
    // A = 32 * log2(e): work in scaled units so exp(-32*d) == ex2(-|xs - ts|)
    const float A = 46.166241308446828f;

    float accC = 0.0f;   // scaled center abs-diffs
    float accL = 0.0f;   // sum of lg2(softmin-sum)

    for (unsigned g = blockIdx.x * GTHREADS + threadIdx.x; g < N_VEC;
         g += GBLOCKS * GTHREADS)
    {
        unsigned row = g / VPR;          // flattened (b, i) row in [0, 64*2048)
        unsigned jj  = g - row * VPR;    // float4 slot within row, [0, 20)
        unsigned i   = row & (T_LEN - 1);

        const float* ip = in + (size_t)row * DDIM + jj * 4;
        const float* tp = tg + (size_t)row * DDIM + jj * 4;

        float4 x4 = *reinterpret_cast<const float4*>(ip);
        float xs[4] = {A * x4.x, A * x4.y, A * x4.z, A * x4.w};

        // 3 target rows (i-1, i, i+1) x 6 cols (j-1 .. j+4), zero-padded OOB,
        // pre-scaled by A
        float t[3][6];
        const bool upv = (i > 0);
        const bool dnv = (i < T_LEN - 1);
        const bool lv  = (jj > 0);
        const bool rv  = (jj < VPR - 1);

        const float* rows[3] = {tp - DDIM, tp, tp + DDIM};
        const bool   rok[3]  = {upv, true, dnv};

        #pragma unroll
        for (int r = 0; r < 3; r++) {
            if (rok[r]) {
                float4 t4 = *reinterpret_cast<const float4*>(rows[r]);
                t[r][1] = A * t4.x; t[r][2] = A * t4.y;
                t[r][3] = A * t4.z; t[r][4] = A * t4.w;
                t[r][0] = lv ? A * rows[r][-1] : 0.0f;
                t[r][5] = rv ? A * rows[r][4]  : 0.0f;
            } else {
                #pragma unroll
                for (int c = 0; c < 6; c++) t[r][c] = 0.0f;
            }
        }

        #pragma unroll
        for (int e = 0; e < 4; e++) {
            float xv = xs[e];
            // center term (dy=0, dx=0): reuse its diff for both accumulators
            float dc = xv - t[1][e + 1];
            accC += fabsf(dc);
            float s = ex2f(-fabsf(dc));
            // remaining 8 shifts
            s += ex2f(-fabsf(xv - t[0][e + 0]));
            s += ex2f(-fabsf(xv - t[0][e + 1]));
            s += ex2f(-fabsf(xv - t[0][e + 2]));
            s += ex2f(-fabsf(xv - t[1][e + 0]));
            s += ex2f(-fabsf(xv - t[1][e + 2]));
            s += ex2f(-fabsf(xv - t[2][e + 0]));
            s += ex2f(-fabsf(xv - t[2][e + 1]));
            s += ex2f(-fabsf(xv - t[2][e + 2]));
            accL += lg2f(fmaxf(s, 1e-37f));
        }
    }

    // deterministic block-level tree reduction of both accumulators
    __shared__ float shc[GTHREADS];
    __shared__ float shl[GTHREADS];
    shc[threadIdx.x] = accC;
    shl[threadIdx.x] = accL;
    __syncthreads();
    #pragma unroll
    for (int off = GTHREADS / 2; off > 0; off >>= 1) {
        if (threadIdx.x < off) {
            shc[threadIdx.x] += shc[threadIdx.x + off];
            shl[threadIdx.x] += shl[threadIdx.x + off];
        }
        __syncthreads();
    }

    __shared__ bool isLast;
    if (threadIdx.x == 0) {
        g_pc[blockIdx.x] = shc[0];
        g_pl[blockIdx.x] = shl[0];
        __threadfence();
        unsigned ticket = atomicAdd(&g_count, 1u);
        isLast = (ticket == GBLOCKS - 1);
    }
    __syncthreads();

    if (isLast) {
        // Last block: deterministic final sum over fixed index order
        __shared__ double dc_sh[GTHREADS];
        __shared__ double dl_sh[GTHREADS];
        double dc = 0.0, dl = 0.0;
        for (int i = threadIdx.x; i < GBLOCKS; i += GTHREADS) {
            dc += (double)__ldcg(&g_pc[i]);
            dl += (double)__ldcg(&g_pl[i]);
        }
        dc_sh[threadIdx.x] = dc;
        dl_sh[threadIdx.x] = dl;
        __syncthreads();
        #pragma unroll
        for (int off = GTHREADS / 2; off > 0; off >>= 1) {
            if (threadIdx.x < off) {
                dc_sh[threadIdx.x] += dc_sh[threadIdx.x + off];
                dl_sh[threadIdx.x] += dl_sh[threadIdx.x + off];
            }
            __syncthreads();
        }
        if (threadIdx.x == 0) {
            const double Ad  = 46.166241308446828;
            const double C2d = -0.021660849392498291;  // -ln(2)/32
            double res = (0.5 / (double)N_ELEM) *
                         (dc_sh[0] / Ad + C2d * dl_sh[0]);
            out[0] = (float)res;
            g_count = 0;   // reset ticket for the next (graph-replayed) launch
        }
    }
}

extern "C" void kernel_launch(void* const* d_in, const int* in_sizes, int n_in,
                              void* d_out, int out_size)
{
    const float* in = (const float*)d_in[0];
    const float* tg = (const float*)d_in[1];
    float* out = (float*)d_out;

    jitter_fused<<<GBLOCKS, GTHREADS>>>(in, tg, out);
}